// round 14
// baseline (speedup 1.0000x reference)
#include <cuda_runtime.h>
#include <cuda_fp16.h>
#include <cstdint>

#define BATCH 4
#define CIN   64
#define COUT  64
#define WDIM  512
#define RES   32
#define VOL   (RES*RES*RES)

#define SUP   16                // supersteps (4 cin each)
#define CPS   4                 // cins per superstep
#define KST   7                 // ksteps per superstep (7*16=112 >= 4*27=108)
#define KVAL  108

#define HRW   35                // halo row stride (floats)
#define HPLN  210               // halo plane stride = 6*HRW
#define HSZ   630               // halo floats per cin (3 planes)
#define HSTG  (CPS*HSZ)         // 2520 floats per stage
#define BSTG  896               // uint4 per B stage (7*4*32)

// ---------------------------------------------------------------------------
// device globals
// ---------------------------------------------------------------------------
__device__ float g_styles[BATCH * CIN];
// per (b,sup): 896 uint4 of fp16 B fragments, fused-K layout
__device__ uint4 g_Bh[BATCH * SUP * BSTG];

__device__ __forceinline__ uint32_t packh2(float lo, float hi) {
    uint32_t d;
    asm("cvt.rn.f16x2.f32 %0, %1, %2;" : "=r"(d) : "f"(hi), "f"(lo));
    return d;
}
__device__ __forceinline__ uint32_t smem_u32(const void* p) {
    uint32_t a;
    asm("{ .reg .u64 t; cvta.to.shared.u64 t, %1; cvt.u32.u64 %0, t; }" : "=r"(a) : "l"(p));
    return a;
}
#define CP_ASYNC4(dst, src) \
    asm volatile("cp.async.ca.shared.global [%0], [%1], 4;" :: "r"(dst), "l"(src) : "memory")
#define CP_ASYNC16(dst, src) \
    asm volatile("cp.async.cg.shared.global [%0], [%1], 16;" :: "r"(dst), "l"(src) : "memory")
#define CP_COMMIT() asm volatile("cp.async.commit_group;" ::: "memory")
#define CP_WAIT0()  asm volatile("cp.async.wait_group 0;" ::: "memory")

__device__ __forceinline__ void mma_f16(float* c, uint32_t a0, uint32_t a1,
                                        uint32_t a2, uint32_t a3,
                                        uint32_t b0, uint32_t b1) {
    asm volatile(
        "mma.sync.aligned.m16n8k16.row.col.f32.f16.f16.f32 "
        "{%0,%1,%2,%3}, {%4,%5,%6,%7}, {%8,%9}, {%0,%1,%2,%3};"
        : "+f"(c[0]), "+f"(c[1]), "+f"(c[2]), "+f"(c[3])
        : "r"(a0), "r"(a1), "r"(a2), "r"(a3), "r"(b0), "r"(b1));
}

// ---------------------------------------------------------------------------
// Kernel A: styles
// ---------------------------------------------------------------------------
__global__ void k_styles(const float* __restrict__ wl,
                         const float* __restrict__ aw,
                         const float* __restrict__ ab) {
    const int b = blockIdx.x >> 6, c = blockIdx.x & 63;
    const int tid = threadIdx.x;                 // 128
    float acc = 0.f;
    for (int j = tid; j < WDIM; j += 128)
        acc += wl[b * WDIM + j] * aw[c * WDIM + j];
#pragma unroll
    for (int o = 16; o; o >>= 1) acc += __shfl_xor_sync(0xffffffffu, acc, o);
    __shared__ float s[4];
    if ((tid & 31) == 0) s[tid >> 5] = acc;
    __syncthreads();
    if (tid == 0)
        g_styles[blockIdx.x] = (s[0] + s[1] + s[2] + s[3]) * 0.044194173824159216f + ab[c];
}

// ---------------------------------------------------------------------------
// Kernel B: modulate + demodulate -> fused-K fp16 B-fragment layout
// ---------------------------------------------------------------------------
__global__ void k_wmod(const float* __restrict__ weight) {
    const int b  = blockIdx.x >> 6;
    const int co = blockIdx.x & 63;
    const int tid = threadIdx.x;                 // 256
    __shared__ float s_sty[CIN];
    __shared__ float s_red[8];
    if (tid < CIN) s_sty[tid] = g_styles[b * CIN + tid];
    __syncthreads();
    const float* wr = weight + co * (CIN * 27);
    float s = 0.f;
    for (int i = tid; i < CIN * 27; i += 256) {
        float v = wr[i] * s_sty[i / 27];
        s += v * v;
    }
#pragma unroll
    for (int o = 16; o; o >>= 1) s += __shfl_xor_sync(0xffffffffu, s, o);
    if ((tid & 31) == 0) s_red[tid >> 5] = s;
    __syncthreads();
    if (tid < 32) {
        float t = (tid < 8) ? s_red[tid] : 0.f;
#pragma unroll
        for (int o = 4; o; o >>= 1) t += __shfl_xor_sync(0xffffffffu, t, o);
        if (tid == 0) s_red[0] = t;
    }
    __syncthreads();
    const float d = rsqrtf(s_red[0] + 1e-8f);
    const int nt = co >> 3;
    const int rr = co & 7;
    // items: (sup, ks, c) -> one uint2; 16*7*4 = 448 items
    uint2* gB2 = (uint2*)(g_Bh + (size_t)b * SUP * BSTG);
    for (int i = tid; i < SUP * KST * 4; i += 256) {
        const int sup = i / 28;
        const int rem = i - sup * 28;
        const int ks  = rem >> 2;
        const int c   = rem & 3;
        float w[4];
        const int kk[4] = {2 * c, 2 * c + 1, 2 * c + 8, 2 * c + 9};
#pragma unroll
        for (int j = 0; j < 4; j++) {
            const int kg = ks * 16 + kk[j];
            if (kg < KVAL) {
                const int cin = sup * CPS + kg / 27;
                const int tap = kg % 27;
                w[j] = wr[cin * 27 + tap] * s_sty[cin] * d;
            } else w[j] = 0.f;
        }
        uint2 v;
        v.x = packh2(w[0], w[1]);
        v.y = packh2(w[2], w[3]);
        const int lane = rr * 4 + c;
        const int slot = (((ks * 4 + (nt >> 1)) * 32 + lane) << 1) + (nt & 1);
        gB2[(size_t)sup * (BSTG * 2) + slot] = v;
    }
}

// ---------------------------------------------------------------------------
// Kernel C: implicit-GEMM conv, mma.sync fp16 m16n8k16, fused-K supersteps
//   CTA: 128 thr / 4 warps; 16 supersteps x 7 ksteps; 2-stage cp.async ring
//   Occupancy 4 (vs 3): waves 3 -> 2, CTA-slot utilization 77% -> 86%.
// ---------------------------------------------------------------------------
__global__ void __launch_bounds__(128, 4)
k_conv(const float* __restrict__ x,
       const float* __restrict__ noise,
       const float* __restrict__ bias,
       float* __restrict__ out) {
    __shared__ float s_halo[2 * HSTG];      // 2 stages x 2520 floats (20160 B)
    __shared__ uint4 s_B[2 * BSTG];         // 2 stages x 14336 B

    const int tid = threadIdx.x;
    const int wid = tid >> 5;
    const int lid = tid & 31;
    const int r   = lid >> 2;
    const int c   = lid & 3;
    const int z   = blockIdx.x >> 3;
    const int y0  = (blockIdx.x & 7) << 2;
    const int b   = blockIdx.y;
    const int y   = y0 + wid;

    const uint32_t sb_halo = smem_u32(s_halo);
    const uint32_t sb_B    = smem_u32(s_B);

    // Per-thread halo staging map (5 elems per cin; i = tid + k*128 < 612)
    int hidx[5], gofs[5];
#pragma unroll
    for (int k = 0; k < 5; k++) {
        const int i = tid + k * 128;
        if (i < 612) {
            const int hz = i / 204, r2 = i - hz * 204;
            const int hy = r2 / 34,  hx = r2 - hy * 34;
            hidx[k] = hz * HPLN + hy * HRW + hx;
            const int gz = z - 1 + hz, gy = y0 - 1 + hy, gx = hx - 1;
            gofs[k] = ((unsigned)gz < RES && (unsigned)gy < RES && (unsigned)gx < RES)
                      ? gz * 1024 + gy * 32 + gx : -1;
        } else { hidx[k] = -1; gofs[k] = -1; }
    }

    // Per-thread tap offsets within a stage for each (ks, j); fused K.
    // kg >= 108 -> offset 0 (B columns there are zero)
    int offs[KST][4];
#pragma unroll
    for (int ks = 0; ks < KST; ks++) {
        const int kk[4] = {2 * c, 2 * c + 1, 2 * c + 8, 2 * c + 9};
#pragma unroll
        for (int j = 0; j < 4; j++) {
            const int kg = ks * 16 + kk[j];
            if (kg < KVAL) {
                const int cinl = kg / 27;
                const int tap  = kg % 27;
                const int dz = tap / 9, rm = tap % 9;
                offs[ks][j] = cinl * HSZ + dz * HPLN + (wid + rm / 3) * HRW + (rm % 3);
            } else offs[ks][j] = 0;
        }
    }

    float acc[2][8][4];
#pragma unroll
    for (int mt = 0; mt < 2; mt++)
#pragma unroll
        for (int nt = 0; nt < 8; nt++)
#pragma unroll
            for (int k = 0; k < 4; k++) acc[mt][nt][k] = 0.f;

    const float* xb = x + (size_t)b * CIN * VOL;
    const uint4* gB = g_Bh + (size_t)b * SUP * BSTG;

    // ---- zero both halo stages (padding slots stay zero forever) ----
    for (int i = tid; i < 2 * HSTG; i += 128) s_halo[i] = 0.f;
    __syncthreads();

    // ---- async superstep issue ----
    auto issue = [&](int s) {
        const int buf = s & 1;
#pragma unroll
        for (int cl = 0; cl < CPS; cl++) {
            const float* xc = xb + (size_t)(s * CPS + cl) * VOL;
            const uint32_t dbase = sb_halo + (buf * HSTG + cl * HSZ) * 4;
#pragma unroll
            for (int k = 0; k < 5; k++)
                if (gofs[k] >= 0)
                    CP_ASYNC4(dbase + hidx[k] * 4, xc + gofs[k]);
        }
        const uint4* bsrc = gB + (size_t)s * BSTG;
        const uint32_t bdst = sb_B + buf * BSTG * 16;
#pragma unroll
        for (int k = 0; k < 7; k++)
            CP_ASYNC16(bdst + (tid + k * 128) * 16, bsrc + tid + k * 128);
        CP_COMMIT();
    };

    issue(0);

#pragma unroll 1
    for (int s = 0; s < SUP; s++) {
        CP_WAIT0();          // stage s landed
        __syncthreads();     // all warps done with buffer (s+1)&1 from superstep s-1

        if (s + 1 < SUP) issue(s + 1);   // overlaps the long compute below

        const float* H  = s_halo + (s & 1) * HSTG;
        const uint4* Bq = s_B + (s & 1) * BSTG;

#pragma unroll
        for (int ks = 0; ks < KST; ks++) {
            uint4 bq[4];
#pragma unroll
            for (int pr = 0; pr < 4; pr++)
                bq[pr] = Bq[((ks << 2) + pr) * 32 + lid];
            const int o0 = offs[ks][0], o1 = offs[ks][1];
            const int o2 = offs[ks][2], o3 = offs[ks][3];
#pragma unroll
            for (int mt = 0; mt < 2; mt++) {
                const int base = (mt << 4) + r;
                const float h0 = H[o0 + base],     h1 = H[o1 + base];
                const float h2 = H[o2 + base],     h3 = H[o3 + base];
                const float g0 = H[o0 + base + 8], g1 = H[o1 + base + 8];
                const float g2 = H[o2 + base + 8], g3 = H[o3 + base + 8];
                const uint32_t a0 = packh2(h0, h1);
                const uint32_t a1 = packh2(g0, g1);
                const uint32_t a2 = packh2(h2, h3);
                const uint32_t a3 = packh2(g2, g3);
#pragma unroll
                for (int pr = 0; pr < 4; pr++) {
                    mma_f16(acc[mt][2 * pr],     a0, a1, a2, a3, bq[pr].x, bq[pr].y);
                    mma_f16(acc[mt][2 * pr + 1], a0, a1, a2, a3, bq[pr].z, bq[pr].w);
                }
            }
        }
    }

    // ---- epilogue: + noise + bias, lrelu(0.2) * sqrt(2) ----
    const float gain = 1.4142135623730951f;
    const int vrow = z * 1024 + y * 32;
    float nzv[2][2];
#pragma unroll
    for (int mt = 0; mt < 2; mt++) {
        nzv[mt][0] = noise[b * VOL + vrow + (mt << 4) + r];
        nzv[mt][1] = noise[b * VOL + vrow + (mt << 4) + r + 8];
    }
    float2 bp[8];
#pragma unroll
    for (int nt = 0; nt < 8; nt++)
        bp[nt] = *(const float2*)(bias + nt * 8 + 2 * c);

#pragma unroll
    for (int nt = 0; nt < 8; nt++) {
        const int co0 = nt * 8 + 2 * c;
        float* o0 = out + ((size_t)(b * COUT + co0) * VOL) + vrow;
#pragma unroll
        for (int mt = 0; mt < 2; mt++) {
            const int xo = (mt << 4) + r;
            float v0 = acc[mt][nt][0] + nzv[mt][0] + bp[nt].x;
            float v1 = acc[mt][nt][1] + nzv[mt][0] + bp[nt].y;
            float v2 = acc[mt][nt][2] + nzv[mt][1] + bp[nt].x;
            float v3 = acc[mt][nt][3] + nzv[mt][1] + bp[nt].y;
            o0[xo]           = (v0 > 0.f ? v0 : 0.2f * v0) * gain;
            o0[VOL + xo]     = (v1 > 0.f ? v1 : 0.2f * v1) * gain;
            o0[xo + 8]       = (v2 > 0.f ? v2 : 0.2f * v2) * gain;
            o0[VOL + xo + 8] = (v3 > 0.f ? v3 : 0.2f * v3) * gain;
        }
    }
}

// ---------------------------------------------------------------------------
extern "C" void kernel_launch(void* const* d_in, const int* in_sizes, int n_in,
                              void* d_out, int out_size) {
    const float* x      = (const float*)d_in[0];
    const float* wl     = (const float*)d_in[1];
    const float* weight = (const float*)d_in[2];
    const float* aw     = (const float*)d_in[3];
    const float* ab     = (const float*)d_in[4];
    const float* noise  = (const float*)d_in[5];
    const float* bias   = (const float*)d_in[6];
    float* out = (float*)d_out;

    k_styles<<<BATCH * CIN, 128>>>(wl, aw, ab);
    k_wmod<<<BATCH * COUT, 256>>>(weight);
    k_conv<<<dim3(256, BATCH), 128>>>(x, noise, bias, out);
}

// round 15
// speedup vs baseline: 1.0058x; 1.0058x over previous
#include <cuda_runtime.h>
#include <cuda_fp16.h>
#include <cstdint>

#define BATCH 4
#define CIN   64
#define COUT  64
#define WDIM  512
#define RES   32
#define VOL   (RES*RES*RES)

#define SUP   16                // supersteps (4 cin each)
#define CPS   4                 // cins per superstep
#define KST   7                 // ksteps per superstep (7*16=112 >= 4*27=108)
#define KVAL  108

#define HRW   34                // halo row stride (floats) -> identity staging map
#define HPLN  204               // 6*HRW
#define HSZ   612               // halo floats per cin (3 planes)
#define HSTG  (CPS*HSZ)         // 2448 floats per stage
#define BSTG  896               // uint4 per B stage (7*4*32)

// dynamic smem layout (bytes)
#define SM_HALO 0
#define SM_B    19584           // 2*HSTG*4
#define SM_OFFS 48256           // SM_B + 2*BSTG*16
#define SM_TOT  50048           // SM_OFFS + 112*16

// ---------------------------------------------------------------------------
// device globals
// ---------------------------------------------------------------------------
// per (b,sup): 896 uint4 of fp16 B fragments, fused-K layout
__device__ uint4 g_Bh[BATCH * SUP * BSTG];

__device__ __forceinline__ uint32_t packh2(float lo, float hi) {
    uint32_t d;
    asm("cvt.rn.f16x2.f32 %0, %1, %2;" : "=r"(d) : "f"(hi), "f"(lo));
    return d;
}
__device__ __forceinline__ uint32_t smem_u32(const void* p) {
    uint32_t a;
    asm("{ .reg .u64 t; cvta.to.shared.u64 t, %1; cvt.u32.u64 %0, t; }" : "=r"(a) : "l"(p));
    return a;
}
#define CP_ASYNC4(dst, src) \
    asm volatile("cp.async.ca.shared.global [%0], [%1], 4;" :: "r"(dst), "l"(src) : "memory")
#define CP_ASYNC16(dst, src) \
    asm volatile("cp.async.cg.shared.global [%0], [%1], 16;" :: "r"(dst), "l"(src) : "memory")
#define CP_COMMIT() asm volatile("cp.async.commit_group;" ::: "memory")
#define CP_WAIT0()  asm volatile("cp.async.wait_group 0;" ::: "memory")

__device__ __forceinline__ void mma_f16(float* c, uint32_t a0, uint32_t a1,
                                        uint32_t a2, uint32_t a3,
                                        uint32_t b0, uint32_t b1) {
    asm volatile(
        "mma.sync.aligned.m16n8k16.row.col.f32.f16.f16.f32 "
        "{%0,%1,%2,%3}, {%4,%5,%6,%7}, {%8,%9}, {%0,%1,%2,%3};"
        : "+f"(c[0]), "+f"(c[1]), "+f"(c[2]), "+f"(c[3])
        : "r"(a0), "r"(a1), "r"(a2), "r"(a3), "r"(b0), "r"(b1));
}

// ---------------------------------------------------------------------------
// Kernel B: styles (computed in-block) + modulate/demodulate -> fused-K B frags
// ---------------------------------------------------------------------------
__global__ void k_wmod(const float* __restrict__ weight,
                       const float* __restrict__ wl,
                       const float* __restrict__ aw,
                       const float* __restrict__ ab) {
    const int b  = blockIdx.x >> 6;
    const int co = blockIdx.x & 63;
    const int tid = threadIdx.x;                 // 256
    const int wrp = tid >> 5;
    const int lid = tid & 31;
    __shared__ float s_sty[CIN];
    __shared__ float s_red[8];

    // styles for batch b: warp wrp computes cins wrp*8 .. wrp*8+7
#pragma unroll 1
    for (int q = 0; q < 8; q++) {
        const int cin = wrp * 8 + q;
        float dot = 0.f;
        for (int j = lid; j < WDIM; j += 32)
            dot += wl[b * WDIM + j] * aw[cin * WDIM + j];
#pragma unroll
        for (int o = 16; o; o >>= 1) dot += __shfl_xor_sync(0xffffffffu, dot, o);
        if (lid == 0)
            s_sty[cin] = dot * 0.044194173824159216f + ab[cin];
    }
    __syncthreads();

    const float* wr = weight + co * (CIN * 27);
    float s = 0.f;
    for (int i = tid; i < CIN * 27; i += 256) {
        float v = wr[i] * s_sty[i / 27];
        s += v * v;
    }
#pragma unroll
    for (int o = 16; o; o >>= 1) s += __shfl_xor_sync(0xffffffffu, s, o);
    if ((tid & 31) == 0) s_red[tid >> 5] = s;
    __syncthreads();
    if (tid < 32) {
        float t = (tid < 8) ? s_red[tid] : 0.f;
#pragma unroll
        for (int o = 4; o; o >>= 1) t += __shfl_xor_sync(0xffffffffu, t, o);
        if (tid == 0) s_red[0] = t;
    }
    __syncthreads();
    const float d = rsqrtf(s_red[0] + 1e-8f);
    const int nt = co >> 3;
    const int rr = co & 7;
    uint2* gB2 = (uint2*)(g_Bh + (size_t)b * SUP * BSTG);
    for (int i = tid; i < SUP * KST * 4; i += 256) {
        const int sup = i / 28;
        const int rem = i - sup * 28;
        const int ks  = rem >> 2;
        const int c   = rem & 3;
        float w[4];
        const int kk[4] = {2 * c, 2 * c + 1, 2 * c + 8, 2 * c + 9};
#pragma unroll
        for (int j = 0; j < 4; j++) {
            const int kg = ks * 16 + kk[j];
            if (kg < KVAL) {
                const int cin = sup * CPS + kg / 27;
                const int tap = kg % 27;
                w[j] = wr[cin * 27 + tap] * s_sty[cin] * d;
            } else w[j] = 0.f;
        }
        uint2 v;
        v.x = packh2(w[0], w[1]);
        v.y = packh2(w[2], w[3]);
        const int lane = rr * 4 + c;
        const int slot = (((ks * 4 + (nt >> 1)) * 32 + lane) << 1) + (nt & 1);
        gB2[(size_t)sup * (BSTG * 2) + slot] = v;
    }
}

// ---------------------------------------------------------------------------
// Kernel C: implicit-GEMM conv, mma.sync fp16 m16n8k16, fused-K supersteps
//   occ 4, offs table in smem (reg relief), dynamic smem 50048 B
// ---------------------------------------------------------------------------
__global__ void __launch_bounds__(128, 4)
k_conv(const float* __restrict__ x,
       const float* __restrict__ noise,
       const float* __restrict__ bias,
       float* __restrict__ out) {
    extern __shared__ char smem[];
    float* s_halo = (float*)(smem + SM_HALO);
    uint4* s_B    = (uint4*)(smem + SM_B);
    uint4* s_offs = (uint4*)(smem + SM_OFFS);

    const int tid = threadIdx.x;
    const int wid = tid >> 5;
    const int lid = tid & 31;
    const int r   = lid >> 2;
    const int c   = lid & 3;
    const int z   = blockIdx.x >> 3;
    const int y0  = (blockIdx.x & 7) << 2;
    const int b   = blockIdx.y;
    const int y   = y0 + wid;

    const uint32_t sb_halo = smem_u32(smem + SM_HALO);
    const uint32_t sb_B    = smem_u32(smem + SM_B);

    // Per-thread halo gmem offsets (identity smem map: slot i = tid + k*128)
    int gofs[5];
#pragma unroll
    for (int k = 0; k < 5; k++) {
        const int i = tid + k * 128;
        if (i < HSZ) {
            const int hz = i / HPLN, r2 = i - hz * HPLN;
            const int hy = r2 / HRW,  hx = r2 - hy * HRW;
            const int gz = z - 1 + hz, gy = y0 - 1 + hy, gx = hx - 1;
            gofs[k] = ((unsigned)gz < RES && (unsigned)gy < RES && (unsigned)gx < RES)
                      ? gz * 1024 + gy * 32 + gx : -1;
        } else gofs[k] = -1;
    }

    // ---- zero both halo stages + build offs table ----
    for (int i = tid; i < 2 * HSTG; i += 128) s_halo[i] = 0.f;
    if (tid < 16) {
        const int twid = tid >> 2, tc = tid & 3;
#pragma unroll
        for (int ks = 0; ks < KST; ks++) {
            int o[4];
            const int kk[4] = {2 * tc, 2 * tc + 1, 2 * tc + 8, 2 * tc + 9};
#pragma unroll
            for (int j = 0; j < 4; j++) {
                const int kg = ks * 16 + kk[j];
                if (kg < KVAL) {
                    const int cinl = kg / 27;
                    const int tap  = kg % 27;
                    const int dz = tap / 9, rm = tap % 9;
                    o[j] = cinl * HSZ + dz * HPLN + (twid + rm / 3) * HRW + (rm % 3);
                } else o[j] = 0;
            }
            s_offs[(twid * 4 + tc) * KST + ks] =
                make_uint4((unsigned)o[0], (unsigned)o[1], (unsigned)o[2], (unsigned)o[3]);
        }
    }
    __syncthreads();

    float acc[2][8][4];
#pragma unroll
    for (int mt = 0; mt < 2; mt++)
#pragma unroll
        for (int nt = 0; nt < 8; nt++)
#pragma unroll
            for (int k = 0; k < 4; k++) acc[mt][nt][k] = 0.f;

    const float* xb = x + (size_t)b * CIN * VOL;
    const uint4* gB = g_Bh + (size_t)b * SUP * BSTG;

    // ---- async superstep issue ----
    auto issue = [&](int s) {
        const int buf = s & 1;
#pragma unroll
        for (int cl = 0; cl < CPS; cl++) {
            const float* xc = xb + (size_t)(s * CPS + cl) * VOL;
            const uint32_t dbase = sb_halo + (buf * HSTG + cl * HSZ) * 4;
#pragma unroll
            for (int k = 0; k < 5; k++)
                if (gofs[k] >= 0)
                    CP_ASYNC4(dbase + (tid + k * 128) * 4, xc + gofs[k]);
        }
        const uint4* bsrc = gB + (size_t)s * BSTG;
        const uint32_t bdst = sb_B + buf * BSTG * 16;
#pragma unroll
        for (int k = 0; k < 7; k++)
            CP_ASYNC16(bdst + (tid + k * 128) * 16, bsrc + tid + k * 128);
        CP_COMMIT();
    };

    issue(0);

#pragma unroll 1
    for (int s = 0; s < SUP; s++) {
        CP_WAIT0();          // stage s landed
        __syncthreads();     // all warps done with buffer (s+1)&1 from superstep s-1

        if (s + 1 < SUP) issue(s + 1);   // overlaps the long compute below

        const float* H  = s_halo + (s & 1) * HSTG;
        const uint4* Bq = s_B + (s & 1) * BSTG;

#pragma unroll
        for (int ks = 0; ks < KST; ks++) {
            uint4 bq[4];
#pragma unroll
            for (int pr = 0; pr < 4; pr++)
                bq[pr] = Bq[((ks << 2) + pr) * 32 + lid];
            const uint4 oq = s_offs[(wid * 4 + c) * KST + ks];
            const int o0 = (int)oq.x, o1 = (int)oq.y;
            const int o2 = (int)oq.z, o3 = (int)oq.w;
#pragma unroll
            for (int mt = 0; mt < 2; mt++) {
                const int base = (mt << 4) + r;
                const float h0 = H[o0 + base],     h1 = H[o1 + base];
                const float h2 = H[o2 + base],     h3 = H[o3 + base];
                const float g0 = H[o0 + base + 8], g1 = H[o1 + base + 8];
                const float g2 = H[o2 + base + 8], g3 = H[o3 + base + 8];
                const uint32_t a0 = packh2(h0, h1);
                const uint32_t a1 = packh2(g0, g1);
                const uint32_t a2 = packh2(h2, h3);
                const uint32_t a3 = packh2(g2, g3);
#pragma unroll
                for (int pr = 0; pr < 4; pr++) {
                    mma_f16(acc[mt][2 * pr],     a0, a1, a2, a3, bq[pr].x, bq[pr].y);
                    mma_f16(acc[mt][2 * pr + 1], a0, a1, a2, a3, bq[pr].z, bq[pr].w);
                }
            }
        }
    }

    // ---- epilogue: + noise + bias, lrelu(0.2) * sqrt(2) ----
    const float gain = 1.4142135623730951f;
    const int vrow = z * 1024 + y * 32;
    float nzv[2][2];
#pragma unroll
    for (int mt = 0; mt < 2; mt++) {
        nzv[mt][0] = noise[b * VOL + vrow + (mt << 4) + r];
        nzv[mt][1] = noise[b * VOL + vrow + (mt << 4) + r + 8];
    }
    float2 bp[8];
#pragma unroll
    for (int nt = 0; nt < 8; nt++)
        bp[nt] = *(const float2*)(bias + nt * 8 + 2 * c);

#pragma unroll
    for (int nt = 0; nt < 8; nt++) {
        const int co0 = nt * 8 + 2 * c;
        float* o0 = out + ((size_t)(b * COUT + co0) * VOL) + vrow;
#pragma unroll
        for (int mt = 0; mt < 2; mt++) {
            const int xo = (mt << 4) + r;
            float v0 = acc[mt][nt][0] + nzv[mt][0] + bp[nt].x;
            float v1 = acc[mt][nt][1] + nzv[mt][0] + bp[nt].y;
            float v2 = acc[mt][nt][2] + nzv[mt][1] + bp[nt].x;
            float v3 = acc[mt][nt][3] + nzv[mt][1] + bp[nt].y;
            o0[xo]           = (v0 > 0.f ? v0 : 0.2f * v0) * gain;
            o0[VOL + xo]     = (v1 > 0.f ? v1 : 0.2f * v1) * gain;
            o0[xo + 8]       = (v2 > 0.f ? v2 : 0.2f * v2) * gain;
            o0[VOL + xo + 8] = (v3 > 0.f ? v3 : 0.2f * v3) * gain;
        }
    }
}

// ---------------------------------------------------------------------------
extern "C" void kernel_launch(void* const* d_in, const int* in_sizes, int n_in,
                              void* d_out, int out_size) {
    const float* x      = (const float*)d_in[0];
    const float* wl     = (const float*)d_in[1];
    const float* weight = (const float*)d_in[2];
    const float* aw     = (const float*)d_in[3];
    const float* ab     = (const float*)d_in[4];
    const float* noise  = (const float*)d_in[5];
    const float* bias   = (const float*)d_in[6];
    float* out = (float*)d_out;

    cudaFuncSetAttribute(k_conv, cudaFuncAttributeMaxDynamicSharedMemorySize, SM_TOT);

    k_wmod<<<BATCH * COUT, 256>>>(weight, wl, aw, ab);
    k_conv<<<dim3(256, BATCH), 128, SM_TOT>>>(x, noise, bias, out);
}

// round 17
// speedup vs baseline: 1.1415x; 1.1349x over previous
#include <cuda_runtime.h>
#include <cuda_fp16.h>
#include <cstdint>

#define BATCH 4
#define CIN   64
#define COUT  64
#define WDIM  512
#define RES   32
#define VOL   (RES*RES*RES)

#define SUP   16                // supersteps (4 cin each)
#define CPS   4                 // cins per superstep
#define KST   7                 // ksteps per superstep (7*16=112 >= 108)
#define KVAL  108

#define HRW   40                // halo row stride: dy -> +8 banks
#define HPLN  240               // 6*HRW:          dz -> +16 banks
#define HSZ   728               // padded cin stride: cin -> +24 banks
#define HSTG  (CPS*HSZ)         // 2912 floats per stage
#define BSTG  896               // uint4 per B stage (7*4*32)

// dynamic smem layout (bytes)
#define SM_HALO 0
#define SM_B    23296           // 2*HSTG*4
#define SM_TOT  51968           // SM_B + 2*BSTG*16

// bank-class row tables: rows (dz*3+dy) whose (2dz+dy)%4 == s
__device__ __constant__ int ROWL[4][3] = {{0,5,6},{1,7,0},{2,3,8},{4,0,0}};
__device__ __constant__ int ROWN[4]    = {3,2,3,1};

// decode: class c, row index rv (0..8) -> (cinl, dz*3+dy)
__device__ __forceinline__ void class_row(int c, int rv, int& cinl, int& row) {
    cinl = 0; row = 0;
#pragma unroll
    for (int ci = 0; ci < 4; ci++) {
        const int s = (c + ci) & 3;
        const int n = ROWN[s];
        if (rv < n) { cinl = ci; row = ROWL[s][rv]; return; }
        rv -= n;
    }
}

// ---------------------------------------------------------------------------
// device globals
// ---------------------------------------------------------------------------
__device__ uint4 g_Bh[BATCH * SUP * BSTG];

__device__ __forceinline__ uint32_t packh2(float lo, float hi) {
    uint32_t d;
    asm("cvt.rn.f16x2.f32 %0, %1, %2;" : "=r"(d) : "f"(hi), "f"(lo));
    return d;
}
__device__ __forceinline__ uint32_t smem_u32(const void* p) {
    uint32_t a;
    asm("{ .reg .u64 t; cvta.to.shared.u64 t, %1; cvt.u32.u64 %0, t; }" : "=r"(a) : "l"(p));
    return a;
}
#define CP_ASYNC4(dst, src) \
    asm volatile("cp.async.ca.shared.global [%0], [%1], 4;" :: "r"(dst), "l"(src) : "memory")
#define CP_ASYNC16(dst, src) \
    asm volatile("cp.async.cg.shared.global [%0], [%1], 16;" :: "r"(dst), "l"(src) : "memory")
#define CP_COMMIT() asm volatile("cp.async.commit_group;" ::: "memory")
#define CP_WAIT0()  asm volatile("cp.async.wait_group 0;" ::: "memory")

__device__ __forceinline__ void mma_f16(float* c, uint32_t a0, uint32_t a1,
                                        uint32_t a2, uint32_t a3,
                                        uint32_t b0, uint32_t b1) {
    asm volatile(
        "mma.sync.aligned.m16n8k16.row.col.f32.f16.f16.f32 "
        "{%0,%1,%2,%3}, {%4,%5,%6,%7}, {%8,%9}, {%0,%1,%2,%3};"
        : "+f"(c[0]), "+f"(c[1]), "+f"(c[2]), "+f"(c[3])
        : "r"(a0), "r"(a1), "r"(a2), "r"(a3), "r"(b0), "r"(b1));
}

// ---------------------------------------------------------------------------
// Kernel B: styles (in-block) + modulate/demodulate -> permuted fp16 B frags
// ---------------------------------------------------------------------------
__global__ void k_wmod(const float* __restrict__ weight,
                       const float* __restrict__ wl,
                       const float* __restrict__ aw,
                       const float* __restrict__ ab) {
    const int b  = blockIdx.x >> 6;
    const int co = blockIdx.x & 63;
    const int tid = threadIdx.x;                 // 256
    const int wrp = tid >> 5;
    const int lid = tid & 31;
    __shared__ float s_sty[CIN];
    __shared__ float s_red[8];

#pragma unroll 1
    for (int q = 0; q < 8; q++) {
        const int cin = wrp * 8 + q;
        float dot = 0.f;
        for (int j = lid; j < WDIM; j += 32)
            dot += wl[b * WDIM + j] * aw[cin * WDIM + j];
#pragma unroll
        for (int o = 16; o; o >>= 1) dot += __shfl_xor_sync(0xffffffffu, dot, o);
        if (lid == 0)
            s_sty[cin] = dot * 0.044194173824159216f + ab[cin];
    }
    __syncthreads();

    const float* wr = weight + co * (CIN * 27);
    float s = 0.f;
    for (int i = tid; i < CIN * 27; i += 256) {
        float v = wr[i] * s_sty[i / 27];
        s += v * v;
    }
#pragma unroll
    for (int o = 16; o; o >>= 1) s += __shfl_xor_sync(0xffffffffu, s, o);
    if ((tid & 31) == 0) s_red[tid >> 5] = s;
    __syncthreads();
    if (tid < 32) {
        float t = (tid < 8) ? s_red[tid] : 0.f;
#pragma unroll
        for (int o = 4; o; o >>= 1) t += __shfl_xor_sync(0xffffffffu, t, o);
        if (tid == 0) s_red[0] = t;
    }
    __syncthreads();
    const float d = rsqrtf(s_red[0] + 1e-8f);
    const int nt = co >> 3;
    const int rr = co & 7;
    uint2* gB2 = (uint2*)(g_Bh + (size_t)b * SUP * BSTG);
    // items: (sup, ks, c); slot (ks,c,j) holds sigma value v = j*7+ks of class c
    for (int i = tid; i < SUP * KST * 4; i += 256) {
        const int sup = i / 28;
        const int rem = i - sup * 28;
        const int ks  = rem >> 2;
        const int c   = rem & 3;
        float w[4];
#pragma unroll
        for (int j = 0; j < 4; j++) {
            const int v = j * 7 + ks;
            if (v < 27) {
                int cinl, row;
                class_row(c, v / 3, cinl, row);
                const int tap = row * 3 + (v % 3);
                const int cin = sup * CPS + cinl;
                w[j] = wr[cin * 27 + tap] * s_sty[cin] * d;
            } else w[j] = 0.f;
        }
        uint2 v2;
        v2.x = packh2(w[0], w[1]);
        v2.y = packh2(w[2], w[3]);
        const int lane = rr * 4 + c;
        const int slot = (((ks * 4 + (nt >> 1)) * 32 + lane) << 1) + (nt & 1);
        gB2[(size_t)sup * (BSTG * 2) + slot] = v2;
    }
}

// ---------------------------------------------------------------------------
// Kernel C: implicit-GEMM conv, mma.sync fp16 m16n8k16, fused-K supersteps
//   Bank-class permuted A-gathers: every A LDS is conflict-free. occ 3.
//   Halo stages zero-filled ONCE at start: boundary (out-of-volume) slots are
//   never written by cp.async and must read as 0.
// ---------------------------------------------------------------------------
__global__ void __launch_bounds__(128, 3)
k_conv(const float* __restrict__ x,
       const float* __restrict__ noise,
       const float* __restrict__ bias,
       float* __restrict__ out) {
    extern __shared__ char smem[];
    float* s_halo = (float*)(smem + SM_HALO);
    uint4* s_B    = (uint4*)(smem + SM_B);

    const int tid = threadIdx.x;
    const int wid = tid >> 5;
    const int lid = tid & 31;
    const int r   = lid >> 2;
    const int c   = lid & 3;
    const int z   = blockIdx.x >> 3;
    const int y0  = (blockIdx.x & 7) << 2;
    const int b   = blockIdx.y;
    const int y   = y0 + wid;

    const uint32_t sb_halo = smem_u32(smem + SM_HALO);
    const uint32_t sb_B    = smem_u32(smem + SM_B);

    // Per-thread halo staging map (612 valid elems per cin)
    int hidx[5], gofs[5];
#pragma unroll
    for (int k = 0; k < 5; k++) {
        const int i = tid + k * 128;
        if (i < 612) {
            const int hz = i / 204, r2 = i - hz * 204;
            const int hy = r2 / 34,  hx = r2 - hy * 34;
            hidx[k] = hz * HPLN + hy * HRW + hx;
            const int gz = z - 1 + hz, gy = y0 - 1 + hy, gx = hx - 1;
            gofs[k] = ((unsigned)gz < RES && (unsigned)gy < RES && (unsigned)gx < RES)
                      ? gz * 1024 + gy * 32 + gx : -1;
        } else { hidx[k] = -1; gofs[k] = -1; }
    }

    // Per-thread tap offsets via bank-class permutation; v>=27 -> offset 0
    int offs[KST][4];
#pragma unroll
    for (int ks = 0; ks < KST; ks++)
#pragma unroll
        for (int j = 0; j < 4; j++) {
            const int v = j * 7 + ks;
            if (v < 27) {
                int cinl, row;
                class_row(c, v / 3, cinl, row);
                const int dz = row / 3, dy = row % 3;
                offs[ks][j] = cinl * HSZ + dz * HPLN + (wid + dy) * HRW + (v % 3);
            } else offs[ks][j] = 0;
        }

    float acc[2][8][4];
#pragma unroll
    for (int mt = 0; mt < 2; mt++)
#pragma unroll
        for (int nt = 0; nt < 8; nt++)
#pragma unroll
            for (int k = 0; k < 4; k++) acc[mt][nt][k] = 0.f;

    const float* xb = x + (size_t)b * CIN * VOL;
    const uint4* gB = g_Bh + (size_t)b * SUP * BSTG;

    // ---- zero both halo stages ONCE (boundary slots stay zero forever) ----
    for (int i = tid; i < 2 * HSTG; i += 128) s_halo[i] = 0.f;
    __syncthreads();

    // ---- async superstep issue ----
    auto issue = [&](int s) {
        const int buf = s & 1;
#pragma unroll
        for (int cl = 0; cl < CPS; cl++) {
            const float* xc = xb + (size_t)(s * CPS + cl) * VOL;
            const uint32_t dbase = sb_halo + (buf * HSTG + cl * HSZ) * 4;
#pragma unroll
            for (int k = 0; k < 5; k++)
                if (gofs[k] >= 0)
                    CP_ASYNC4(dbase + hidx[k] * 4, xc + gofs[k]);
        }
        const uint4* bsrc = gB + (size_t)s * BSTG;
        const uint32_t bdst = sb_B + buf * BSTG * 16;
#pragma unroll
        for (int k = 0; k < 7; k++)
            CP_ASYNC16(bdst + (tid + k * 128) * 16, bsrc + tid + k * 128);
        CP_COMMIT();
    };

    issue(0);

#pragma unroll 1
    for (int s = 0; s < SUP; s++) {
        CP_WAIT0();
        __syncthreads();

        if (s + 1 < SUP) issue(s + 1);

        const float* H  = s_halo + (s & 1) * HSTG;
        const uint4* Bq = s_B + (s & 1) * BSTG;

#pragma unroll
        for (int ks = 0; ks < KST; ks++) {
            uint4 bq[4];
#pragma unroll
            for (int pr = 0; pr < 4; pr++)
                bq[pr] = Bq[((ks << 2) + pr) * 32 + lid];
            const int o0 = offs[ks][0], o1 = offs[ks][1];
            const int o2 = offs[ks][2], o3 = offs[ks][3];
#pragma unroll
            for (int mt = 0; mt < 2; mt++) {
                const int base = (mt << 4) + r;
                const float h0 = H[o0 + base],     h1 = H[o1 + base];
                const float h2 = H[o2 + base],     h3 = H[o3 + base];
                const float g0 = H[o0 + base + 8], g1 = H[o1 + base + 8];
                const float g2 = H[o2 + base + 8], g3 = H[o3 + base + 8];
                const uint32_t a0 = packh2(h0, h1);
                const uint32_t a1 = packh2(g0, g1);
                const uint32_t a2 = packh2(h2, h3);
                const uint32_t a3 = packh2(g2, g3);
#pragma unroll
                for (int pr = 0; pr < 4; pr++) {
                    mma_f16(acc[mt][2 * pr],     a0, a1, a2, a3, bq[pr].x, bq[pr].y);
                    mma_f16(acc[mt][2 * pr + 1], a0, a1, a2, a3, bq[pr].z, bq[pr].w);
                }
            }
        }
    }

    // ---- epilogue: + noise + bias, lrelu(0.2) * sqrt(2) ----
    const float gain = 1.4142135623730951f;
    const int vrow = z * 1024 + y * 32;
    float nzv[2][2];
#pragma unroll
    for (int mt = 0; mt < 2; mt++) {
        nzv[mt][0] = noise[b * VOL + vrow + (mt << 4) + r];
        nzv[mt][1] = noise[b * VOL + vrow + (mt << 4) + r + 8];
    }
    float2 bp[8];
#pragma unroll
    for (int nt = 0; nt < 8; nt++)
        bp[nt] = *(const float2*)(bias + nt * 8 + 2 * c);

#pragma unroll
    for (int nt = 0; nt < 8; nt++) {
        const int co0 = nt * 8 + 2 * c;
        float* o0 = out + ((size_t)(b * COUT + co0) * VOL) + vrow;
#pragma unroll
        for (int mt = 0; mt < 2; mt++) {
            const int xo = (mt << 4) + r;
            float v0 = acc[mt][nt][0] + nzv[mt][0] + bp[nt].x;
            float v1 = acc[mt][nt][1] + nzv[mt][0] + bp[nt].y;
            float v2 = acc[mt][nt][2] + nzv[mt][1] + bp[nt].x;
            float v3 = acc[mt][nt][3] + nzv[mt][1] + bp[nt].y;
            o0[xo]           = (v0 > 0.f ? v0 : 0.2f * v0) * gain;
            o0[VOL + xo]     = (v1 > 0.f ? v1 : 0.2f * v1) * gain;
            o0[xo + 8]       = (v2 > 0.f ? v2 : 0.2f * v2) * gain;
            o0[VOL + xo + 8] = (v3 > 0.f ? v3 : 0.2f * v3) * gain;
        }
    }
}

// ---------------------------------------------------------------------------
extern "C" void kernel_launch(void* const* d_in, const int* in_sizes, int n_in,
                              void* d_out, int out_size) {
    const float* x      = (const float*)d_in[0];
    const float* wl     = (const float*)d_in[1];
    const float* weight = (const float*)d_in[2];
    const float* aw     = (const float*)d_in[3];
    const float* ab     = (const float*)d_in[4];
    const float* noise  = (const float*)d_in[5];
    const float* bias   = (const float*)d_in[6];
    float* out = (float*)d_out;

    cudaFuncSetAttribute(k_conv, cudaFuncAttributeMaxDynamicSharedMemorySize, SM_TOT);

    k_wmod<<<BATCH * COUT, 256>>>(weight, wl, aw, ab);
    k_conv<<<dim3(256, BATCH), 128, SM_TOT>>>(x, noise, bias, out);
}